// round 12
// baseline (speedup 1.0000x reference)
#include <cuda_runtime.h>
#include <cuda_fp16.h>
#include <cstdint>

#define B_ 32
#define N_ 4096
#define M_ 256
#define L_ 128
#define H_ 4
#define NCH 32

// Scratch (no runtime allocations allowed)
__device__ __align__(256) __half g_Wh[H_ * 256 * 256];         // [h][col(2L interleaved)][k] fp16 (512KB)
__device__ __align__(256) __half g_xh[(size_t)B_ * N_ * M_];   // fp16 x (67MB)
__device__ float g_lp[2 * B_ * H_ * N_];                       // partial logits per N-half (4MB)
__device__ float g_part[B_ * NCH * H_ * M_];                   // 4MB
__device__ int   g_idx[B_ * N_];                               // compacted row indices per batch
__device__ int   g_cnt[B_];                                    // masked-in counts

// ---------------------------------------------------------------------------
__device__ __forceinline__ uint32_t smem_u32(const void* p) {
    uint32_t a;
    asm("{ .reg .u64 t; cvta.to.shared.u64 t, %1; cvt.u32.u64 %0, t; }" : "=r"(a) : "l"(p));
    return a;
}
__device__ __forceinline__ void cp16(uint32_t s, const void* g) {
    asm volatile("cp.async.cg.shared.global [%0], [%1], 16;" :: "r"(s), "l"(g));
}
__device__ __forceinline__ void ldm4(uint32_t& r0, uint32_t& r1, uint32_t& r2, uint32_t& r3,
                                     uint32_t a) {
    asm volatile("ldmatrix.sync.aligned.m8n8.x4.shared.b16 {%0,%1,%2,%3}, [%4];"
                 : "=r"(r0), "=r"(r1), "=r"(r2), "=r"(r3) : "r"(a));
}
__device__ __forceinline__ __half2 h2tanh_ap(__half2 x) {
    uint32_t xi = *(uint32_t*)&x, ri;
    asm("tanh.approx.f16x2 %0, %1;" : "=r"(ri) : "r"(xi));
    return *(__half2*)&ri;
}

#define MMA_F16(C_, A_, b0_, b1_)                                             \
    asm volatile("mma.sync.aligned.m16n8k16.row.col.f32.f16.f16.f32 "         \
                 "{%0,%1,%2,%3}, {%4,%5,%6,%7}, {%8,%9}, {%0,%1,%2,%3};"      \
                 : "+f"((C_)[0]), "+f"((C_)[1]), "+f"((C_)[2]), "+f"((C_)[3]) \
                 : "r"((A_)[0]), "r"((A_)[1]), "r"((A_)[2]), "r"((A_)[3]),    \
                   "r"(b0_), "r"(b1_))

// ---------------------------------------------------------------------------
// Kernel 0a: transpose-pack W_h[h][2l+c][k] = fp16((c? U : V)[h][k][l])
// ---------------------------------------------------------------------------
__global__ void pack_w_kernel(const float* __restrict__ V, const float* __restrict__ U) {
    __shared__ float tv[32][33], tu[32][33];
    int h = blockIdx.z, k0 = blockIdx.x * 32, l0 = blockIdx.y * 32;
    int tx = threadIdx.x, ty = threadIdx.y;
    tv[ty][tx] = V[h * M_ * L_ + (k0 + ty) * L_ + l0 + tx];
    tu[ty][tx] = U[h * M_ * L_ + (k0 + ty) * L_ + l0 + tx];
    __syncthreads();
    int c = 2 * (l0 + ty);
    g_Wh[h * 65536 + c * 256 + k0 + tx]       = __float2half_rn(tv[tx][ty]);
    g_Wh[h * 65536 + (c + 1) * 256 + k0 + tx] = __float2half_rn(tu[tx][ty]);
}

// Kernel 0b: convert x -> fp16 scratch, skipping masked-out rows
__global__ __launch_bounds__(1024) void cvt_x_kernel(
    const float* __restrict__ x, const float* __restrict__ masks)
{
    size_t i = (size_t)blockIdx.x * 1024 + threadIdx.x;   // < 8388608 float4s
    size_t row = i >> 6;                                  // 64 float4 per row
    if (masks[row] == 0.0f) return;
    float4 v = ((const float4*)x)[i];
    __half2 h0 = __floats2half2_rn(v.x, v.y);
    __half2 h1 = __floats2half2_rn(v.z, v.w);
    uint2 o;
    o.x = *(uint32_t*)&h0;
    o.y = *(uint32_t*)&h1;
    ((uint2*)g_xh)[i] = o;
}

// Kernel 0c: per-batch compaction of masked-in row indices (deterministic scan)
__global__ __launch_bounds__(1024) void compact_kernel(const float* __restrict__ masks) {
    const int b = blockIdx.x;
    const int tid = threadIdx.x;
    const int lane = tid & 31, wid = tid >> 5;
    __shared__ int wsum[32];

    int n0 = tid * 4;
    int m0 = masks[b * N_ + n0 + 0] != 0.0f;
    int m1 = masks[b * N_ + n0 + 1] != 0.0f;
    int m2 = masks[b * N_ + n0 + 2] != 0.0f;
    int m3 = masks[b * N_ + n0 + 3] != 0.0f;
    int cnt = m0 + m1 + m2 + m3;

    int sc = cnt;
    #pragma unroll
    for (int o = 1; o < 32; o <<= 1) {
        int v = __shfl_up_sync(0xffffffffu, sc, o);
        if (lane >= o) sc += v;
    }
    if (lane == 31) wsum[wid] = sc;
    __syncthreads();
    if (tid < 32) {
        int v = wsum[tid];
        #pragma unroll
        for (int o = 1; o < 32; o <<= 1) {
            int t = __shfl_up_sync(0xffffffffu, v, o);
            if (lane >= o) v += t;
        }
        wsum[tid] = v;
        if (tid == 31) g_cnt[b] = v;
    }
    __syncthreads();
    int off = (wid ? wsum[wid - 1] : 0) + (sc - cnt);
    int* dst = g_idx + b * N_;
    if (m0) dst[off] = n0;
    off += m0;
    if (m1) dst[off] = n0 + 1;
    off += m1;
    if (m2) dst[off] = n0 + 2;
    off += m2;
    if (m3) dst[off] = n0 + 3;
}

// ---------------------------------------------------------------------------
// Kernel 1: fp16 mma GEMM over COMPACTED rows, RESIDENT-W multi-tile blocks,
//   cross-jblk A prefetch, packed-f16x2 tanh epilogue.
//   Per block: one (h, nhalf) W tile resident in smem; JGRP row-tiles of 128
//   gathered rows. 256 threads, 8 warps (4x2, 32x64 tiles), 3-stage A
//   cp.async, 2 CTAs/SM. Writes PARTIAL logit per N-half to g_lp.
// ---------------------------------------------------------------------------
#define WROWB 528                     // W smem row stride (256 fp16 + 16B pad)
#define W_BYTES (128 * WROWB)         // 67584
#define ROWB 80                       // A smem row stride (32 fp16 + 16B pad)
#define A_B (128 * ROWB)              // 10240
#define SMEM_BYTES (W_BYTES + 3 * A_B)  // 98304
#define JGRP 4                        // jblks per block

__global__ __launch_bounds__(256, 2) void gemm_logits_kernel(const float* __restrict__ w) {
    const int h     = blockIdx.x >> 1;
    const int nhalf = blockIdx.x & 1;
    const int b     = blockIdx.y;
    const int jbase = blockIdx.z * JGRP;
    const int cnt   = g_cnt[b];
    if (jbase * 128 >= cnt) return;

    extern __shared__ char smc[];
    const uint32_t smb  = smem_u32(smc);          // W region
    const uint32_t smA  = smb + W_BYTES;          // A stages
    float* smr = (float*)(smc + W_BYTES + 2 * A_B);  // reduce buffer (stage-2 region)
    const int tid = threadIdx.x;
    const int wrp = tid >> 5, lane = tid & 31;
    const int g = lane >> 2, tig = lane & 3;
    const int wr = wrp & 3, wc = wrp >> 2;        // 4 x 2 warp grid (32x64 tiles)

    __shared__ float ws_s[64];
    __shared__ int sidxb[2][128];
    if (tid < 64) ws_s[tid] = w[h * L_ + nhalf * 64 + tid];

    const __half* wh = g_Wh + h * 65536 + nhalf * 128 * 256;

    // Load resident W tile (128 rows x 512B, padded stride 528B), group 0
    #pragma unroll
    for (int i = 0; i < 16; i++) {
        int u = tid + i * 256;                    // 0..4095 16B-units
        int row = u >> 5, col = u & 31;
        cp16(smb + row * WROWB + col * 16, wh + row * 256 + col * 8);
    }
    asm volatile("cp.async.commit_group;" ::: "memory");

    // first jblk's indices
    if (tid >= 128) sidxb[0][tid - 128] = g_idx[b * N_ + jbase * 128 + (tid - 128)];
    __syncthreads();

    // ldmatrix lane-address components
    const int mrowL = wr * 32 + (lane & 15);
    const uint32_t ahalf = (uint32_t)((lane >> 4) << 4);
    const int nrowL = wc * 64 + ((lane >> 4) << 3) + (lane & 7);
    const uint32_t bhalf = (uint32_t)(((lane >> 3) & 1) << 4);

    const __half2 half05 = __floats2half2_rn(0.5f, 0.5f);

#define ISSUE_A(c_, s_, p0_, p1_) do {                                            \
        uint32_t bs_ = smA + (uint32_t)(s_) * A_B;                                \
        int sg_ = tid & 3, r_ = tid >> 2;                                         \
        cp16(bs_ + r_ * ROWB + sg_ * 16, (p0_) + (c_) * 32 + sg_ * 8);            \
        cp16(bs_ + (64 + r_) * ROWB + sg_ * 16, (p1_) + (c_) * 32 + sg_ * 8);     \
        asm volatile("cp.async.commit_group;" ::: "memory");                      \
    } while (0)

#define COMPUTE(c_, s_) do {                                                      \
        const uint32_t pa_ = smA + (uint32_t)(s_) * A_B;                          \
        _Pragma("unroll")                                                         \
        for (int ks = 0; ks < 2; ks++) {                                          \
            uint32_t af[2][4];                                                    \
            _Pragma("unroll")                                                     \
            for (int mt = 0; mt < 2; mt++)                                        \
                ldm4(af[mt][0], af[mt][1], af[mt][2], af[mt][3],                  \
                     pa_ + (uint32_t)(mrowL + mt * 16) * ROWB + ks * 32 + ahalf); \
            _Pragma("unroll")                                                     \
            for (int p = 0; p < 4; p++) {                                         \
                uint32_t b0, b1, b2, b3;                                          \
                ldm4(b0, b1, b2, b3,                                              \
                     smb + (uint32_t)(nrowL + p * 16) * WROWB                     \
                         + (c_) * 64 + ks * 32 + bhalf);                          \
                _Pragma("unroll")                                                 \
                for (int mt = 0; mt < 2; mt++) {                                  \
                    MMA_F16(C[mt][2 * p],     af[mt], b0, b1);                    \
                    MMA_F16(C[mt][2 * p + 1], af[mt], b2, b3);                    \
                }                                                                 \
            }                                                                     \
        }                                                                         \
    } while (0)

#define BODY(W_)                                                                  \
        asm volatile("cp.async.wait_group " #W_ ";" ::: "memory");                \
        __syncthreads();

    {
        // prologue A for jblk 0
        const int* sid0 = sidxb[0];
        const __half* xp0 = g_xh + ((size_t)b * N_ + sid0[tid >> 2]) * 256;
        const __half* xp1 = g_xh + ((size_t)b * N_ + sid0[64 + (tid >> 2)]) * 256;
        ISSUE_A(0, 0, xp0, xp1);
        ISSUE_A(1, 1, xp0, xp1);
    }

    for (int jj = 0; jj < JGRP; jj++) {
        const int jblk = jbase + jj;
        if (jblk * 128 >= cnt) break;
        const bool more = (jj + 1 < JGRP) && ((jblk + 1) * 128 < cnt);

        const int* sid = sidxb[jj & 1];
        const __half* xr0 = g_xh + ((size_t)b * N_ + sid[tid >> 2]) * 256;
        const __half* xr1 = g_xh + ((size_t)b * N_ + sid[64 + (tid >> 2)]) * 256;

        // prefetch next jblk's indices (made visible by mainloop barriers)
        if (more && tid >= 128)
            sidxb[(jj + 1) & 1][tid - 128] =
                g_idx[b * N_ + (jblk + 1) * 128 + (tid - 128)];

        float C[2][8][4];
        #pragma unroll
        for (int mt = 0; mt < 2; mt++)
            #pragma unroll
            for (int nt = 0; nt < 8; nt++)
                #pragma unroll
                for (int q = 0; q < 4; q++) C[mt][nt][q] = 0.0f;

        // chunk c uses stage (c % 3); lookahead 2
        BODY(1); ISSUE_A(2, 2, xr0, xr1); COMPUTE(0, 0);
        BODY(1); ISSUE_A(3, 0, xr0, xr1); COMPUTE(1, 1);
        BODY(1); ISSUE_A(4, 1, xr0, xr1); COMPUTE(2, 2);
        BODY(1); ISSUE_A(5, 2, xr0, xr1); COMPUTE(3, 0);
        BODY(1); ISSUE_A(6, 0, xr0, xr1); COMPUTE(4, 1);
        BODY(1); ISSUE_A(7, 1, xr0, xr1); COMPUTE(5, 2);
        BODY(1);                          COMPUTE(6, 0);
        BODY(0);                          COMPUTE(7, 1);

        // Register epilogue: f = tanh(yv)*sigmoid(yu), sigmoid = 0.5+0.5*tanh(u/2)
        // Packed f16x2 over row-pair (g, g+8): c0/c2 = V, c1/c3 = U.
        float part[2][2];
        part[0][0] = part[0][1] = part[1][0] = part[1][1] = 0.f;
        #pragma unroll
        for (int mt = 0; mt < 2; mt++)
            #pragma unroll
            for (int nt = 0; nt < 8; nt++) {
                float wl = ws_s[wc * 32 + nt * 4 + tig];
                __half2 v2 = __floats2half2_rn(C[mt][nt][0], C[mt][nt][2]);
                __half2 u2 = __floats2half2_rn(0.5f * C[mt][nt][1], 0.5f * C[mt][nt][3]);
                __half2 tv2 = h2tanh_ap(v2);
                __half2 s2  = __hfma2(h2tanh_ap(u2), half05, half05);
                float2 f2 = __half22float2(__hmul2(tv2, s2));
                part[mt][0] = fmaf(f2.x, wl, part[mt][0]);
                part[mt][1] = fmaf(f2.y, wl, part[mt][1]);
            }
        #pragma unroll
        for (int mt = 0; mt < 2; mt++)
            #pragma unroll
            for (int rh = 0; rh < 2; rh++) {
                part[mt][rh] += __shfl_xor_sync(0xffffffffu, part[mt][rh], 1);
                part[mt][rh] += __shfl_xor_sync(0xffffffffu, part[mt][rh], 2);
            }

        __syncthreads();   // all COMPUTE(7,1) done; stages 0/1 free; sidx_next visible

        if (more) {        // overlap next jblk's pipeline fill with reduce+store
            const int* sidn = sidxb[(jj + 1) & 1];
            const __half* xn0 = g_xh + ((size_t)b * N_ + sidn[tid >> 2]) * 256;
            const __half* xn1 = g_xh + ((size_t)b * N_ + sidn[64 + (tid >> 2)]) * 256;
            ISSUE_A(0, 0, xn0, xn1);
            ISSUE_A(1, 1, xn0, xn1);
        }

        if (tig == 0) {
            #pragma unroll
            for (int mt = 0; mt < 2; mt++) {
                smr[wc * 128 + wr * 32 + mt * 16 + g]     = part[mt][0];
                smr[wc * 128 + wr * 32 + mt * 16 + 8 + g] = part[mt][1];
            }
        }
        __syncthreads();
        if (tid < 128 && jblk * 128 + tid < cnt) {
            float lg = smr[tid] + smr[128 + tid];
            g_lp[((nhalf * B_ + b) * H_ + h) * N_ + sid[tid]] = lg;
        }
    }
#undef ISSUE_A
#undef COMPUTE
#undef BODY
}

// ---------------------------------------------------------------------------
// Kernel 2: a = e^2/sum(e^2), e = (m ? exp(lp0+lp1) : 0). Writes att (H,B,N).
// ---------------------------------------------------------------------------
__global__ __launch_bounds__(512) void attn_kernel(
    const float* __restrict__ masks, float* __restrict__ out_att)
{
    const int bh = blockIdx.x;
    const int b = bh >> 2, h = bh & 3;
    const int tid = threadIdx.x;
    __shared__ float red[16];

    float e2[8];
    float s = 0.0f;
    #pragma unroll
    for (int i = 0; i < 8; i++) {
        int n = tid + i * 512;
        float m = masks[b * N_ + n];
        float e = 0.0f;
        if (m != 0.0f) {
            float lg = g_lp[bh * N_ + n] + g_lp[(B_ * H_ + bh) * N_ + n];
            e = expf(lg);
        }
        e2[i] = e * e;
        s += e2[i];
    }
    #pragma unroll
    for (int o = 16; o > 0; o >>= 1) s += __shfl_xor_sync(0xffffffffu, s, o);
    if ((tid & 31) == 0) red[tid >> 5] = s;
    __syncthreads();
    if (tid < 32) {
        float v = (tid < 16) ? red[tid] : 0.0f;
        #pragma unroll
        for (int o = 8; o > 0; o >>= 1) v += __shfl_xor_sync(0xffffffffu, v, o);
        if (tid == 0) red[0] = 1.0f / v;
    }
    __syncthreads();
    float inv = red[0];
    #pragma unroll
    for (int i = 0; i < 8; i++) {
        int n = tid + i * 512;
        out_att[(h * B_ + b) * N_ + n] = e2[i] * inv;
    }
}

// ---------------------------------------------------------------------------
// Kernel 3: emb partials from fp16 x (dense; NCH chunks of 128 n each)
// ---------------------------------------------------------------------------
__global__ __launch_bounds__(256) void emb_partial_kernel(const float* __restrict__ att) {
    const int chunk = blockIdx.x;
    const int b     = blockIdx.y;
    const int tid   = threadIdx.x;  // = m
    __shared__ float a_s[H_][N_ / NCH];

    const int n0 = chunk * (N_ / NCH);
    for (int t = tid; t < H_ * (N_ / NCH); t += 256) {
        int hh = t >> 7, nn = t & 127;
        a_s[hh][nn] = att[(hh * B_ + b) * N_ + n0 + nn];
    }
    __syncthreads();

    float a0 = 0.f, a1 = 0.f, a2 = 0.f, a3 = 0.f;
    const __half* xp = g_xh + ((size_t)b * N_ + n0) * M_ + tid;
    #pragma unroll 4
    for (int n = 0; n < N_ / NCH; n++) {
        float xv = __half2float(xp[(size_t)n * M_]);
        a0 += a_s[0][n] * xv;
        a1 += a_s[1][n] * xv;
        a2 += a_s[2][n] * xv;
        a3 += a_s[3][n] * xv;
    }
    float* pp = g_part + ((b * NCH + chunk) * H_) * M_ + tid;
    pp[0]      = a0;
    pp[M_]     = a1;
    pp[2 * M_] = a2;
    pp[3 * M_] = a3;
}

// ---------------------------------------------------------------------------
// Kernel 4: reduce partials -> emb (B, H*M)
// ---------------------------------------------------------------------------
__global__ void emb_reduce_kernel(float* __restrict__ out_emb) {
    int idx = blockIdx.x * blockDim.x + threadIdx.x;  // < 32768
    int b  = idx >> 10;
    int hm = idx & 1023;
    float s = 0.0f;
    #pragma unroll
    for (int c = 0; c < NCH; c++)
        s += g_part[(b * NCH + c) * (H_ * M_) + hm];
    out_emb[idx] = s;
}

// ---------------------------------------------------------------------------
extern "C" void kernel_launch(void* const* d_in, const int* in_sizes, int n_in,
                              void* d_out, int out_size) {
    const float* x     = (const float*)d_in[0];
    const float* masks = (const float*)d_in[1];
    const float* V     = (const float*)d_in[2];
    const float* U     = (const float*)d_in[3];
    const float* w     = (const float*)d_in[4];

    float* out     = (float*)d_out;
    float* out_att = out;                        // (H, B, N, 1)
    float* out_emb = out + (size_t)H_ * B_ * N_; // (B, H*M)

    cudaFuncSetAttribute(gemm_logits_kernel,
                         cudaFuncAttributeMaxDynamicSharedMemorySize, SMEM_BYTES);

    pack_w_kernel<<<dim3(8, 4, H_), dim3(32, 32)>>>(V, U);
    cvt_x_kernel<<<8192, 1024>>>(x, masks);
    compact_kernel<<<B_, 1024>>>(masks);

    dim3 g1(H_ * 2, B_, 32 / JGRP);   // (h,nhalf) fastest -> x rows shared via L2
    gemm_logits_kernel<<<g1, 256, SMEM_BYTES>>>(w);

    attn_kernel<<<B_ * H_, 512>>>(masks, out_att);

    emb_partial_kernel<<<dim3(NCH, B_), 256>>>(out_att);

    emb_reduce_kernel<<<32, 1024>>>(out_emb);
}

// round 13
// speedup vs baseline: 1.0166x; 1.0166x over previous
#include <cuda_runtime.h>
#include <cuda_fp16.h>
#include <cstdint>

#define B_ 32
#define N_ 4096
#define M_ 256
#define L_ 128
#define H_ 4
#define NCH 32

// Scratch (no runtime allocations allowed)
__device__ __align__(256) __half g_Wh[H_ * 256 * 256];         // [h][col(2L interleaved)][k] fp16 (512KB)
__device__ __align__(256) __half g_xh[(size_t)B_ * N_ * M_];   // fp16 x (67MB)
__device__ float g_lp[2 * B_ * H_ * N_];                       // partial logits per N-half (4MB)
__device__ float g_part[B_ * NCH * H_ * M_];                   // 4MB
__device__ int   g_idx[B_ * N_];                               // compacted row indices per batch
__device__ int   g_cnt[B_];                                    // masked-in counts

// ---------------------------------------------------------------------------
__device__ __forceinline__ uint32_t smem_u32(const void* p) {
    uint32_t a;
    asm("{ .reg .u64 t; cvta.to.shared.u64 t, %1; cvt.u32.u64 %0, t; }" : "=r"(a) : "l"(p));
    return a;
}
__device__ __forceinline__ void cp16(uint32_t s, const void* g) {
    asm volatile("cp.async.cg.shared.global [%0], [%1], 16;" :: "r"(s), "l"(g));
}
__device__ __forceinline__ void ldm4(uint32_t& r0, uint32_t& r1, uint32_t& r2, uint32_t& r3,
                                     uint32_t a) {
    asm volatile("ldmatrix.sync.aligned.m8n8.x4.shared.b16 {%0,%1,%2,%3}, [%4];"
                 : "=r"(r0), "=r"(r1), "=r"(r2), "=r"(r3) : "r"(a));
}
__device__ __forceinline__ float tanh_ap(float x) {
    float r;
    asm("tanh.approx.f32 %0, %1;" : "=f"(r) : "f"(x));
    return r;
}
__device__ __forceinline__ void pair_bar(int id) {
    asm volatile("bar.sync %0, 64;" :: "r"(id) : "memory");
}

#define MMA_F16(C_, A_, b0_, b1_)                                             \
    asm volatile("mma.sync.aligned.m16n8k16.row.col.f32.f16.f16.f32 "         \
                 "{%0,%1,%2,%3}, {%4,%5,%6,%7}, {%8,%9}, {%0,%1,%2,%3};"      \
                 : "+f"((C_)[0]), "+f"((C_)[1]), "+f"((C_)[2]), "+f"((C_)[3]) \
                 : "r"((A_)[0]), "r"((A_)[1]), "r"((A_)[2]), "r"((A_)[3]),    \
                   "r"(b0_), "r"(b1_))

// ---------------------------------------------------------------------------
// Kernel 0a: transpose-pack W_h[h][2l+c][k] = fp16((c? U : V)[h][k][l])
// ---------------------------------------------------------------------------
__global__ void pack_w_kernel(const float* __restrict__ V, const float* __restrict__ U) {
    __shared__ float tv[32][33], tu[32][33];
    int h = blockIdx.z, k0 = blockIdx.x * 32, l0 = blockIdx.y * 32;
    int tx = threadIdx.x, ty = threadIdx.y;
    tv[ty][tx] = V[h * M_ * L_ + (k0 + ty) * L_ + l0 + tx];
    tu[ty][tx] = U[h * M_ * L_ + (k0 + ty) * L_ + l0 + tx];
    __syncthreads();
    int c = 2 * (l0 + ty);
    g_Wh[h * 65536 + c * 256 + k0 + tx]       = __float2half_rn(tv[tx][ty]);
    g_Wh[h * 65536 + (c + 1) * 256 + k0 + tx] = __float2half_rn(tu[tx][ty]);
}

// Kernel 0b: convert x -> fp16 scratch, skipping masked-out rows
__global__ __launch_bounds__(1024) void cvt_x_kernel(
    const float* __restrict__ x, const float* __restrict__ masks)
{
    size_t i = (size_t)blockIdx.x * 1024 + threadIdx.x;   // < 8388608 float4s
    size_t row = i >> 6;                                  // 64 float4 per row
    if (masks[row] == 0.0f) return;
    float4 v = ((const float4*)x)[i];
    __half2 h0 = __floats2half2_rn(v.x, v.y);
    __half2 h1 = __floats2half2_rn(v.z, v.w);
    uint2 o;
    o.x = *(uint32_t*)&h0;
    o.y = *(uint32_t*)&h1;
    ((uint2*)g_xh)[i] = o;
}

// Kernel 0c: per-batch compaction of masked-in row indices (deterministic scan)
__global__ __launch_bounds__(1024) void compact_kernel(const float* __restrict__ masks) {
    const int b = blockIdx.x;
    const int tid = threadIdx.x;
    const int lane = tid & 31, wid = tid >> 5;
    __shared__ int wsum[32];

    int n0 = tid * 4;
    int m0 = masks[b * N_ + n0 + 0] != 0.0f;
    int m1 = masks[b * N_ + n0 + 1] != 0.0f;
    int m2 = masks[b * N_ + n0 + 2] != 0.0f;
    int m3 = masks[b * N_ + n0 + 3] != 0.0f;
    int cnt = m0 + m1 + m2 + m3;

    int sc = cnt;
    #pragma unroll
    for (int o = 1; o < 32; o <<= 1) {
        int v = __shfl_up_sync(0xffffffffu, sc, o);
        if (lane >= o) sc += v;
    }
    if (lane == 31) wsum[wid] = sc;
    __syncthreads();
    if (tid < 32) {
        int v = wsum[tid];
        #pragma unroll
        for (int o = 1; o < 32; o <<= 1) {
            int t = __shfl_up_sync(0xffffffffu, v, o);
            if (lane >= o) v += t;
        }
        wsum[tid] = v;
        if (tid == 31) g_cnt[b] = v;
    }
    __syncthreads();
    int off = (wid ? wsum[wid - 1] : 0) + (sc - cnt);
    int* dst = g_idx + b * N_;
    if (m0) dst[off] = n0;
    off += m0;
    if (m1) dst[off] = n0 + 1;
    off += m1;
    if (m2) dst[off] = n0 + 2;
    off += m2;
    if (m3) dst[off] = n0 + 3;
}

// ---------------------------------------------------------------------------
// Kernel 1: fp16 mma GEMM over COMPACTED rows. Resident W; PAIR-LOCAL A
//   pipelines with named barriers (no block-wide sync in mainloop).
//   Pair p = warps (wr=p, wc=0/1): 32-row band x 128 cols; 3 A stages of
//   32 rows x 32 fp16 per pair. 256 threads, 2 CTAs/SM, JGRP row-tiles.
// ---------------------------------------------------------------------------
#define WROWB 528                     // W smem row stride (256 fp16 + 16B pad)
#define W_BYTES (128 * WROWB)         // 67584
#define AROWB 80                      // A stage row stride (32 fp16 + 16B pad)
#define ASTG (32 * AROWB)             // 2560 per stage
#define PAIR_B (3 * ASTG)             // 7680 per pair
#define SMEM_BYTES (W_BYTES + 4 * PAIR_B)  // 98304
#define JGRP 4

__global__ __launch_bounds__(256, 2) void gemm_logits_kernel(const float* __restrict__ w) {
    const int h     = blockIdx.x >> 1;
    const int nhalf = blockIdx.x & 1;
    const int b     = blockIdx.y;
    const int jbase = blockIdx.z * JGRP;
    const int cnt   = g_cnt[b];
    if (jbase * 128 >= cnt) return;

    extern __shared__ char smc[];
    const uint32_t smb = smem_u32(smc);           // W region
    const int tid = threadIdx.x;
    const int wrp = tid >> 5, lane = tid & 31;
    const int g = lane >> 2, tig = lane & 3;
    const int wr = wrp & 3, wc = wrp >> 2;        // pair id = wr; col half = wc

    __shared__ float ws_s[64];
    __shared__ float epi[4][32];
    if (tid < 64) ws_s[tid] = w[h * L_ + nhalf * 64 + tid];

    const __half* wh = g_Wh + h * 65536 + nhalf * 128 * 256;

    // Resident W tile load (one group), then block sync for visibility
    #pragma unroll
    for (int i = 0; i < 16; i++) {
        int u = tid + i * 256;                    // 0..4095 16B-units
        int row = u >> 5, col = u & 31;
        cp16(smb + row * WROWB + col * 16, wh + row * 256 + col * 8);
    }
    asm volatile("cp.async.commit_group;" ::: "memory");
    asm volatile("cp.async.wait_group 0;" ::: "memory");
    __syncthreads();                               // only block-wide sync

    const uint32_t pstg = smb + W_BYTES + (uint32_t)wr * PAIR_B;
    const int barid = 1 + wr;

    // A-load lane mapping: band row br (one row per lane-pair), two 16B cols
    const int br   = wc * 16 + (lane >> 1);        // 0..31 within band
    const int c16a = (lane & 1) * 2;               // 16B-col {0,1} or {2,3}

    // ldmatrix lane-address components (band-local A, global W)
    const int mrowL = lane & 15;
    const uint32_t ahalf = (uint32_t)((lane >> 4) << 4);
    const int nrowL = wc * 64 + ((lane >> 4) << 3) + (lane & 7);
    const uint32_t bhalf = (uint32_t)(((lane >> 3) & 1) << 4);

#define ISSUE_A(c_, s_) do {                                                      \
        uint32_t bs_ = pstg + (uint32_t)(s_) * ASTG;                              \
        cp16(bs_ + br * AROWB + c16a * 16,       xr + (c_) * 32 + c16a * 8);      \
        cp16(bs_ + br * AROWB + (c16a + 1) * 16, xr + (c_) * 32 + c16a * 8 + 8);  \
        asm volatile("cp.async.commit_group;" ::: "memory");                      \
    } while (0)

#define COMPUTE(c_, s_) do {                                                      \
        const uint32_t pa_ = pstg + (uint32_t)(s_) * ASTG;                        \
        _Pragma("unroll")                                                         \
        for (int ks = 0; ks < 2; ks++) {                                          \
            uint32_t af[2][4];                                                    \
            _Pragma("unroll")                                                     \
            for (int mt = 0; mt < 2; mt++)                                        \
                ldm4(af[mt][0], af[mt][1], af[mt][2], af[mt][3],                  \
                     pa_ + (uint32_t)(mrowL + mt * 16) * AROWB + ks * 32 + ahalf);\
            _Pragma("unroll")                                                     \
            for (int p = 0; p < 4; p++) {                                         \
                uint32_t b0, b1, b2, b3;                                          \
                ldm4(b0, b1, b2, b3,                                              \
                     smb + (uint32_t)(nrowL + p * 16) * WROWB                     \
                         + (c_) * 64 + ks * 32 + bhalf);                          \
                _Pragma("unroll")                                                 \
                for (int mt = 0; mt < 2; mt++) {                                  \
                    MMA_F16(C[mt][2 * p],     af[mt], b0, b1);                    \
                    MMA_F16(C[mt][2 * p + 1], af[mt], b2, b3);                    \
                }                                                                 \
            }                                                                     \
        }                                                                         \
    } while (0)

#define WAITB(W_)                                                                 \
        asm volatile("cp.async.wait_group " #W_ ";" ::: "memory");                \
        pair_bar(barid);

    for (int jj = 0; jj < JGRP; jj++) {
        const int jblk = jbase + jj;
        if (jblk * 128 >= cnt) break;

        // this lane's gathered A row (stale g_idx entries are valid indices)
        const int ridx = g_idx[b * N_ + jblk * 128 + wr * 32 + br];
        const __half* xr = g_xh + ((size_t)b * N_ + ridx) * 256;

        float C[2][8][4];
        #pragma unroll
        for (int mt = 0; mt < 2; mt++)
            #pragma unroll
            for (int nt = 0; nt < 8; nt++)
                #pragma unroll
                for (int q = 0; q < 4; q++) C[mt][nt][q] = 0.0f;

        ISSUE_A(0, 0); ISSUE_A(1, 1);

        // chunk c uses stage (c % 3); pair-local barriers only
        WAITB(1); ISSUE_A(2, 2); COMPUTE(0, 0);
        WAITB(1); ISSUE_A(3, 0); COMPUTE(1, 1);
        WAITB(1); ISSUE_A(4, 1); COMPUTE(2, 2);
        WAITB(1); ISSUE_A(5, 2); COMPUTE(3, 0);
        WAITB(1); ISSUE_A(6, 0); COMPUTE(4, 1);
        WAITB(1); ISSUE_A(7, 1); COMPUTE(5, 2);
        WAITB(1);                COMPUTE(6, 0);
        WAITB(0);                COMPUTE(7, 1);

        // Epilogue: f = tanh(yv)*sigmoid(yu), sigmoid(u) = 0.5 + 0.5*tanh(u/2)
        float part[2][2];
        part[0][0] = part[0][1] = part[1][0] = part[1][1] = 0.f;
        #pragma unroll
        for (int mt = 0; mt < 2; mt++)
            #pragma unroll
            for (int nt = 0; nt < 8; nt++) {
                float wl = ws_s[wc * 32 + nt * 4 + tig];
                float s0 = fmaf(tanh_ap(0.5f * C[mt][nt][1]), 0.5f, 0.5f);
                float s1 = fmaf(tanh_ap(0.5f * C[mt][nt][3]), 0.5f, 0.5f);
                part[mt][0] = fmaf(tanh_ap(C[mt][nt][0]) * s0, wl, part[mt][0]);
                part[mt][1] = fmaf(tanh_ap(C[mt][nt][2]) * s1, wl, part[mt][1]);
            }
        #pragma unroll
        for (int mt = 0; mt < 2; mt++)
            #pragma unroll
            for (int rh = 0; rh < 2; rh++) {
                part[mt][rh] += __shfl_xor_sync(0xffffffffu, part[mt][rh], 1);
                part[mt][rh] += __shfl_xor_sync(0xffffffffu, part[mt][rh], 2);
            }

        // pair reduce: wc1 -> epi, bar, wc0 adds + stores
        if (wc == 1 && tig == 0) {
            #pragma unroll
            for (int mt = 0; mt < 2; mt++) {
                epi[wr][mt * 16 + g]     = part[mt][0];
                epi[wr][mt * 16 + 8 + g] = part[mt][1];
            }
        }
        pair_bar(barid);
        if (wc == 0 && tig == 0) {
            #pragma unroll
            for (int mt = 0; mt < 2; mt++)
                #pragma unroll
                for (int rh = 0; rh < 2; rh++) {
                    int row = wr * 32 + mt * 16 + rh * 8 + g;
                    if (jblk * 128 + row < cnt) {
                        float lg = part[mt][rh] + epi[wr][mt * 16 + rh * 8 + g];
                        g_lp[((nhalf * B_ + b) * H_ + h) * N_ +
                             g_idx[b * N_ + jblk * 128 + row]] = lg;
                    }
                }
        }
    }
#undef ISSUE_A
#undef COMPUTE
#undef WAITB
}

// ---------------------------------------------------------------------------
// Kernel 2: a = e^2/sum(e^2), e = (m ? exp(lp0+lp1) : 0). Writes att (H,B,N).
// ---------------------------------------------------------------------------
__global__ __launch_bounds__(512) void attn_kernel(
    const float* __restrict__ masks, float* __restrict__ out_att)
{
    const int bh = blockIdx.x;
    const int b = bh >> 2, h = bh & 3;
    const int tid = threadIdx.x;
    __shared__ float red[16];

    float e2[8];
    float s = 0.0f;
    #pragma unroll
    for (int i = 0; i < 8; i++) {
        int n = tid + i * 512;
        float m = masks[b * N_ + n];
        float e = 0.0f;
        if (m != 0.0f) {
            float lg = g_lp[bh * N_ + n] + g_lp[(B_ * H_ + bh) * N_ + n];
            e = expf(lg);
        }
        e2[i] = e * e;
        s += e2[i];
    }
    #pragma unroll
    for (int o = 16; o > 0; o >>= 1) s += __shfl_xor_sync(0xffffffffu, s, o);
    if ((tid & 31) == 0) red[tid >> 5] = s;
    __syncthreads();
    if (tid < 32) {
        float v = (tid < 16) ? red[tid] : 0.0f;
        #pragma unroll
        for (int o = 8; o > 0; o >>= 1) v += __shfl_xor_sync(0xffffffffu, v, o);
        if (tid == 0) red[0] = 1.0f / v;
    }
    __syncthreads();
    float inv = red[0];
    #pragma unroll
    for (int i = 0; i < 8; i++) {
        int n = tid + i * 512;
        out_att[(h * B_ + b) * N_ + n] = e2[i] * inv;
    }
}

// ---------------------------------------------------------------------------
// Kernel 3: emb partials from fp16 x (dense; NCH chunks of 128 n each)
// ---------------------------------------------------------------------------
__global__ __launch_bounds__(256) void emb_partial_kernel(const float* __restrict__ att) {
    const int chunk = blockIdx.x;
    const int b     = blockIdx.y;
    const int tid   = threadIdx.x;  // = m
    __shared__ float a_s[H_][N_ / NCH];

    const int n0 = chunk * (N_ / NCH);
    for (int t = tid; t < H_ * (N_ / NCH); t += 256) {
        int hh = t >> 7, nn = t & 127;
        a_s[hh][nn] = att[(hh * B_ + b) * N_ + n0 + nn];
    }
    __syncthreads();

    float a0 = 0.f, a1 = 0.f, a2 = 0.f, a3 = 0.f;
    const __half* xp = g_xh + ((size_t)b * N_ + n0) * M_ + tid;
    #pragma unroll 4
    for (int n = 0; n < N_ / NCH; n++) {
        float xv = __half2float(xp[(size_t)n * M_]);
        a0 += a_s[0][n] * xv;
        a1 += a_s[1][n] * xv;
        a2 += a_s[2][n] * xv;
        a3 += a_s[3][n] * xv;
    }
    float* pp = g_part + ((b * NCH + chunk) * H_) * M_ + tid;
    pp[0]      = a0;
    pp[M_]     = a1;
    pp[2 * M_] = a2;
    pp[3 * M_] = a3;
}

// ---------------------------------------------------------------------------
// Kernel 4: reduce partials -> emb (B, H*M)
// ---------------------------------------------------------------------------
__global__ void emb_reduce_kernel(float* __restrict__ out_emb) {
    int idx = blockIdx.x * blockDim.x + threadIdx.x;  // < 32768
    int b  = idx >> 10;
    int hm = idx & 1023;
    float s = 0.0f;
    #pragma unroll
    for (int c = 0; c < NCH; c++)
        s += g_part[(b * NCH + c) * (H_ * M_) + hm];
    out_emb[idx] = s;
}

// ---------------------------------------------------------------------------
extern "C" void kernel_launch(void* const* d_in, const int* in_sizes, int n_in,
                              void* d_out, int out_size) {
    const float* x     = (const float*)d_in[0];
    const float* masks = (const float*)d_in[1];
    const float* V     = (const float*)d_in[2];
    const float* U     = (const float*)d_in[3];
    const float* w     = (const float*)d_in[4];

    float* out     = (float*)d_out;
    float* out_att = out;                        // (H, B, N, 1)
    float* out_emb = out + (size_t)H_ * B_ * N_; // (B, H*M)

    cudaFuncSetAttribute(gemm_logits_kernel,
                         cudaFuncAttributeMaxDynamicSharedMemorySize, SMEM_BYTES);

    pack_w_kernel<<<dim3(8, 4, H_), dim3(32, 32)>>>(V, U);
    cvt_x_kernel<<<8192, 1024>>>(x, masks);
    compact_kernel<<<B_, 1024>>>(masks);

    dim3 g1(H_ * 2, B_, 32 / JGRP);   // (h,nhalf) fastest -> x rows shared via L2
    gemm_logits_kernel<<<g1, 256, SMEM_BYTES>>>(w);

    attn_kernel<<<B_ * H_, 512>>>(masks, out_att);

    emb_partial_kernel<<<dim3(NCH, B_), 256>>>(out_att);

    emb_reduce_kernel<<<32, 1024>>>(out_emb);
}

// round 14
// speedup vs baseline: 1.0470x; 1.0299x over previous
#include <cuda_runtime.h>
#include <cuda_fp16.h>
#include <cstdint>

#define B_ 32
#define N_ 4096
#define M_ 256
#define L_ 128
#define H_ 4
#define NCH 32

// Scratch (no runtime allocations allowed)
__device__ __align__(256) __half g_Wh[H_ * 256 * 256];         // [h][col(2L interleaved)][k] fp16 (512KB)
__device__ __align__(256) __half g_xh[(size_t)B_ * N_ * M_];   // fp16 x (67MB)
__device__ float g_lp[2 * B_ * H_ * N_];                       // partial logits per N-half (4MB)
__device__ float g_part[B_ * NCH * H_ * M_];                   // 4MB
__device__ int   g_idx[B_ * N_];                               // compacted row indices per batch
__device__ int   g_cnt[B_];                                    // masked-in counts

// ---------------------------------------------------------------------------
__device__ __forceinline__ uint32_t smem_u32(const void* p) {
    uint32_t a;
    asm("{ .reg .u64 t; cvta.to.shared.u64 t, %1; cvt.u32.u64 %0, t; }" : "=r"(a) : "l"(p));
    return a;
}
__device__ __forceinline__ void cp16(uint32_t s, const void* g) {
    asm volatile("cp.async.cg.shared.global [%0], [%1], 16;" :: "r"(s), "l"(g));
}
__device__ __forceinline__ void ldm4(uint32_t& r0, uint32_t& r1, uint32_t& r2, uint32_t& r3,
                                     uint32_t a) {
    asm volatile("ldmatrix.sync.aligned.m8n8.x4.shared.b16 {%0,%1,%2,%3}, [%4];"
                 : "=r"(r0), "=r"(r1), "=r"(r2), "=r"(r3) : "r"(a));
}
__device__ __forceinline__ float tanh_ap(float x) {
    float r;
    asm("tanh.approx.f32 %0, %1;" : "=f"(r) : "f"(x));
    return r;
}
__device__ __forceinline__ void pair_bar(int id) {
    asm volatile("bar.sync %0, 64;" :: "r"(id) : "memory");
}

#define MMA_F16(C_, A_, b0_, b1_)                                             \
    asm volatile("mma.sync.aligned.m16n8k16.row.col.f32.f16.f16.f32 "         \
                 "{%0,%1,%2,%3}, {%4,%5,%6,%7}, {%8,%9}, {%0,%1,%2,%3};"      \
                 : "+f"((C_)[0]), "+f"((C_)[1]), "+f"((C_)[2]), "+f"((C_)[3]) \
                 : "r"((A_)[0]), "r"((A_)[1]), "r"((A_)[2]), "r"((A_)[3]),    \
                   "r"(b0_), "r"(b1_))

// ---------------------------------------------------------------------------
// Kernel 0 (fused prep): blockIdx.x ranges
//   [0, 8192)       : cvt_x  — x -> fp16 scratch, skipping masked-out rows
//   [8192, 8224)    : compact — per-batch masked-in index scan
//   [8224, 8352)    : pack_w  — transpose-pack V/U interleaved fp16
// All branches use 1024 threads.
// ---------------------------------------------------------------------------
#define PREP_CVT   8192
#define PREP_CMP   (PREP_CVT + B_)          // 8224
#define PREP_TOT   (PREP_CMP + 8 * 4 * H_)  // 8352

__global__ __launch_bounds__(1024) void prep_kernel(
    const float* __restrict__ x, const float* __restrict__ masks,
    const float* __restrict__ V, const float* __restrict__ U)
{
    const int bx  = blockIdx.x;
    const int tid = threadIdx.x;

    if (bx < PREP_CVT) {
        // ---- cvt_x ----
        size_t i = (size_t)bx * 1024 + tid;            // < 8388608 float4s
        size_t row = i >> 6;                           // 64 float4 per row
        if (masks[row] == 0.0f) return;
        float4 v = ((const float4*)x)[i];
        __half2 h0 = __floats2half2_rn(v.x, v.y);
        __half2 h1 = __floats2half2_rn(v.z, v.w);
        uint2 o;
        o.x = *(uint32_t*)&h0;
        o.y = *(uint32_t*)&h1;
        ((uint2*)g_xh)[i] = o;
    } else if (bx < PREP_CMP) {
        // ---- compact (deterministic scan) ----
        const int b = bx - PREP_CVT;
        const int lane = tid & 31, wid = tid >> 5;
        __shared__ int wsum[32];

        int n0 = tid * 4;
        int m0 = masks[b * N_ + n0 + 0] != 0.0f;
        int m1 = masks[b * N_ + n0 + 1] != 0.0f;
        int m2 = masks[b * N_ + n0 + 2] != 0.0f;
        int m3 = masks[b * N_ + n0 + 3] != 0.0f;
        int cnt = m0 + m1 + m2 + m3;

        int sc = cnt;
        #pragma unroll
        for (int o = 1; o < 32; o <<= 1) {
            int v = __shfl_up_sync(0xffffffffu, sc, o);
            if (lane >= o) sc += v;
        }
        if (lane == 31) wsum[wid] = sc;
        __syncthreads();
        if (tid < 32) {
            int v = wsum[tid];
            #pragma unroll
            for (int o = 1; o < 32; o <<= 1) {
                int t = __shfl_up_sync(0xffffffffu, v, o);
                if (lane >= o) v += t;
            }
            wsum[tid] = v;
            if (tid == 31) g_cnt[b] = v;
        }
        __syncthreads();
        int off = (wid ? wsum[wid - 1] : 0) + (sc - cnt);
        int* dst = g_idx + b * N_;
        if (m0) dst[off] = n0;
        off += m0;
        if (m1) dst[off] = n0 + 1;
        off += m1;
        if (m2) dst[off] = n0 + 2;
        off += m2;
        if (m3) dst[off] = n0 + 3;
    } else {
        // ---- pack_w: W_h[h][2l+c][k] = fp16((c? U : V)[h][k][l]) ----
        __shared__ float tv[32][33], tu[32][33];
        int u  = bx - PREP_CMP;            // 0..127 = (kx<4? no: 8) * ...
        int kx = u & 7, ly = (u >> 3) & 3, h = u >> 5;
        int k0 = kx * 32, l0 = ly * 32;
        int tx = tid & 31, ty = tid >> 5;
        tv[ty][tx] = V[h * M_ * L_ + (k0 + ty) * L_ + l0 + tx];
        tu[ty][tx] = U[h * M_ * L_ + (k0 + ty) * L_ + l0 + tx];
        __syncthreads();
        int c = 2 * (l0 + ty);
        g_Wh[h * 65536 + c * 256 + k0 + tx]       = __float2half_rn(tv[tx][ty]);
        g_Wh[h * 65536 + (c + 1) * 256 + k0 + tx] = __float2half_rn(tu[tx][ty]);
    }
}

// ---------------------------------------------------------------------------
// Kernel 1: fp16 mma GEMM over COMPACTED rows. Resident W; PAIR-LOCAL A
//   pipelines with named barriers (no block-wide sync in mainloop).
//   Pair p = warps (wr=p, wc=0/1): 32-row band x 128 cols; 3 A stages of
//   32 rows x 32 fp16 per pair. 256 threads, 2 CTAs/SM, JGRP row-tiles.
// ---------------------------------------------------------------------------
#define WROWB 528                     // W smem row stride (256 fp16 + 16B pad)
#define W_BYTES (128 * WROWB)         // 67584
#define AROWB 80                      // A stage row stride (32 fp16 + 16B pad)
#define ASTG (32 * AROWB)             // 2560 per stage
#define PAIR_B (3 * ASTG)             // 7680 per pair
#define SMEM_BYTES (W_BYTES + 4 * PAIR_B)  // 98304
#define JGRP 4

__global__ __launch_bounds__(256, 2) void gemm_logits_kernel(const float* __restrict__ w) {
    const int h     = blockIdx.x >> 1;
    const int nhalf = blockIdx.x & 1;
    const int b     = blockIdx.y;
    const int jbase = blockIdx.z * JGRP;
    const int cnt   = g_cnt[b];
    if (jbase * 128 >= cnt) return;

    extern __shared__ char smc[];
    const uint32_t smb = smem_u32(smc);           // W region
    const int tid = threadIdx.x;
    const int wrp = tid >> 5, lane = tid & 31;
    const int g = lane >> 2, tig = lane & 3;
    const int wr = wrp & 3, wc = wrp >> 2;        // pair id = wr; col half = wc

    __shared__ float ws_s[64];
    __shared__ float epi[4][32];
    if (tid < 64) ws_s[tid] = w[h * L_ + nhalf * 64 + tid];

    const __half* wh = g_Wh + h * 65536 + nhalf * 128 * 256;

    // Resident W tile load (one group), then block sync for visibility
    #pragma unroll
    for (int i = 0; i < 16; i++) {
        int u = tid + i * 256;                    // 0..4095 16B-units
        int row = u >> 5, col = u & 31;
        cp16(smb + row * WROWB + col * 16, wh + row * 256 + col * 8);
    }
    asm volatile("cp.async.commit_group;" ::: "memory");
    asm volatile("cp.async.wait_group 0;" ::: "memory");
    __syncthreads();                               // only block-wide sync

    const uint32_t pstg = smb + W_BYTES + (uint32_t)wr * PAIR_B;
    const int barid = 1 + wr;

    // A-load lane mapping: band row br (one row per lane-pair), two 16B cols
    const int br   = wc * 16 + (lane >> 1);        // 0..31 within band
    const int c16a = (lane & 1) * 2;               // 16B-col {0,1} or {2,3}

    // ldmatrix lane-address components (band-local A, global W)
    const int mrowL = lane & 15;
    const uint32_t ahalf = (uint32_t)((lane >> 4) << 4);
    const int nrowL = wc * 64 + ((lane >> 4) << 3) + (lane & 7);
    const uint32_t bhalf = (uint32_t)(((lane >> 3) & 1) << 4);

#define ISSUE_A(c_, s_) do {                                                      \
        uint32_t bs_ = pstg + (uint32_t)(s_) * ASTG;                              \
        cp16(bs_ + br * AROWB + c16a * 16,       xr + (c_) * 32 + c16a * 8);      \
        cp16(bs_ + br * AROWB + (c16a + 1) * 16, xr + (c_) * 32 + c16a * 8 + 8);  \
        asm volatile("cp.async.commit_group;" ::: "memory");                      \
    } while (0)

#define COMPUTE(c_, s_) do {                                                      \
        const uint32_t pa_ = pstg + (uint32_t)(s_) * ASTG;                        \
        _Pragma("unroll")                                                         \
        for (int ks = 0; ks < 2; ks++) {                                          \
            uint32_t af[2][4];                                                    \
            _Pragma("unroll")                                                     \
            for (int mt = 0; mt < 2; mt++)                                        \
                ldm4(af[mt][0], af[mt][1], af[mt][2], af[mt][3],                  \
                     pa_ + (uint32_t)(mrowL + mt * 16) * AROWB + ks * 32 + ahalf);\
            _Pragma("unroll")                                                     \
            for (int p = 0; p < 4; p++) {                                         \
                uint32_t b0, b1, b2, b3;                                          \
                ldm4(b0, b1, b2, b3,                                              \
                     smb + (uint32_t)(nrowL + p * 16) * WROWB                     \
                         + (c_) * 64 + ks * 32 + bhalf);                          \
                _Pragma("unroll")                                                 \
                for (int mt = 0; mt < 2; mt++) {                                  \
                    MMA_F16(C[mt][2 * p],     af[mt], b0, b1);                    \
                    MMA_F16(C[mt][2 * p + 1], af[mt], b2, b3);                    \
                }                                                                 \
            }                                                                     \
        }                                                                         \
    } while (0)

#define WAITB(W_)                                                                 \
        asm volatile("cp.async.wait_group " #W_ ";" ::: "memory");                \
        pair_bar(barid);

    for (int jj = 0; jj < JGRP; jj++) {
        const int jblk = jbase + jj;
        if (jblk * 128 >= cnt) break;

        // this lane's gathered A row (stale g_idx entries are valid indices)
        const int ridx = g_idx[b * N_ + jblk * 128 + wr * 32 + br];
        const __half* xr = g_xh + ((size_t)b * N_ + ridx) * 256;

        float C[2][8][4];
        #pragma unroll
        for (int mt = 0; mt < 2; mt++)
            #pragma unroll
            for (int nt = 0; nt < 8; nt++)
                #pragma unroll
                for (int q = 0; q < 4; q++) C[mt][nt][q] = 0.0f;

        ISSUE_A(0, 0); ISSUE_A(1, 1);

        // chunk c uses stage (c % 3); pair-local barriers only
        WAITB(1); ISSUE_A(2, 2); COMPUTE(0, 0);
        WAITB(1); ISSUE_A(3, 0); COMPUTE(1, 1);
        WAITB(1); ISSUE_A(4, 1); COMPUTE(2, 2);
        WAITB(1); ISSUE_A(5, 2); COMPUTE(3, 0);
        WAITB(1); ISSUE_A(6, 0); COMPUTE(4, 1);
        WAITB(1); ISSUE_A(7, 1); COMPUTE(5, 2);
        WAITB(1);                COMPUTE(6, 0);
        WAITB(0);                COMPUTE(7, 1);

        // Epilogue: f = tanh(yv)*sigmoid(yu), sigmoid(u) = 0.5 + 0.5*tanh(u/2)
        float part[2][2];
        part[0][0] = part[0][1] = part[1][0] = part[1][1] = 0.f;
        #pragma unroll
        for (int mt = 0; mt < 2; mt++)
            #pragma unroll
            for (int nt = 0; nt < 8; nt++) {
                float wl = ws_s[wc * 32 + nt * 4 + tig];
                float s0 = fmaf(tanh_ap(0.5f * C[mt][nt][1]), 0.5f, 0.5f);
                float s1 = fmaf(tanh_ap(0.5f * C[mt][nt][3]), 0.5f, 0.5f);
                part[mt][0] = fmaf(tanh_ap(C[mt][nt][0]) * s0, wl, part[mt][0]);
                part[mt][1] = fmaf(tanh_ap(C[mt][nt][2]) * s1, wl, part[mt][1]);
            }
        #pragma unroll
        for (int mt = 0; mt < 2; mt++)
            #pragma unroll
            for (int rh = 0; rh < 2; rh++) {
                part[mt][rh] += __shfl_xor_sync(0xffffffffu, part[mt][rh], 1);
                part[mt][rh] += __shfl_xor_sync(0xffffffffu, part[mt][rh], 2);
            }

        // pair reduce: wc1 -> epi, bar, wc0 adds + stores
        if (wc == 1 && tig == 0) {
            #pragma unroll
            for (int mt = 0; mt < 2; mt++) {
                epi[wr][mt * 16 + g]     = part[mt][0];
                epi[wr][mt * 16 + 8 + g] = part[mt][1];
            }
        }
        pair_bar(barid);
        if (wc == 0 && tig == 0) {
            #pragma unroll
            for (int mt = 0; mt < 2; mt++)
                #pragma unroll
                for (int rh = 0; rh < 2; rh++) {
                    int row = wr * 32 + mt * 16 + rh * 8 + g;
                    if (jblk * 128 + row < cnt) {
                        float lg = part[mt][rh] + epi[wr][mt * 16 + rh * 8 + g];
                        g_lp[((nhalf * B_ + b) * H_ + h) * N_ +
                             g_idx[b * N_ + jblk * 128 + row]] = lg;
                    }
                }
        }
    }
#undef ISSUE_A
#undef COMPUTE
#undef WAITB
}

// ---------------------------------------------------------------------------
// Kernel 2: a = e^2/sum(e^2), e = (m ? exp(lp0+lp1) : 0). Writes att (H,B,N).
// ---------------------------------------------------------------------------
__global__ __launch_bounds__(512) void attn_kernel(
    const float* __restrict__ masks, float* __restrict__ out_att)
{
    const int bh = blockIdx.x;
    const int b = bh >> 2, h = bh & 3;
    const int tid = threadIdx.x;
    __shared__ float red[16];

    float e2[8];
    float s = 0.0f;
    #pragma unroll
    for (int i = 0; i < 8; i++) {
        int n = tid + i * 512;
        float m = masks[b * N_ + n];
        float e = 0.0f;
        if (m != 0.0f) {
            float lg = g_lp[bh * N_ + n] + g_lp[(B_ * H_ + bh) * N_ + n];
            e = expf(lg);
        }
        e2[i] = e * e;
        s += e2[i];
    }
    #pragma unroll
    for (int o = 16; o > 0; o >>= 1) s += __shfl_xor_sync(0xffffffffu, s, o);
    if ((tid & 31) == 0) red[tid >> 5] = s;
    __syncthreads();
    if (tid < 32) {
        float v = (tid < 16) ? red[tid] : 0.0f;
        #pragma unroll
        for (int o = 8; o > 0; o >>= 1) v += __shfl_xor_sync(0xffffffffu, v, o);
        if (tid == 0) red[0] = 1.0f / v;
    }
    __syncthreads();
    float inv = red[0];
    #pragma unroll
    for (int i = 0; i < 8; i++) {
        int n = tid + i * 512;
        out_att[(h * B_ + b) * N_ + n] = e2[i] * inv;
    }
}

// ---------------------------------------------------------------------------
// Kernel 3: emb partials from fp16 x (dense; NCH chunks of 128 n each)
// ---------------------------------------------------------------------------
__global__ __launch_bounds__(256) void emb_partial_kernel(const float* __restrict__ att) {
    const int chunk = blockIdx.x;
    const int b     = blockIdx.y;
    const int tid   = threadIdx.x;  // = m
    __shared__ float a_s[H_][N_ / NCH];

    const int n0 = chunk * (N_ / NCH);
    for (int t = tid; t < H_ * (N_ / NCH); t += 256) {
        int hh = t >> 7, nn = t & 127;
        a_s[hh][nn] = att[(hh * B_ + b) * N_ + n0 + nn];
    }
    __syncthreads();

    float a0 = 0.f, a1 = 0.f, a2 = 0.f, a3 = 0.f;
    const __half* xp = g_xh + ((size_t)b * N_ + n0) * M_ + tid;
    #pragma unroll 4
    for (int n = 0; n < N_ / NCH; n++) {
        float xv = __half2float(xp[(size_t)n * M_]);
        a0 += a_s[0][n] * xv;
        a1 += a_s[1][n] * xv;
        a2 += a_s[2][n] * xv;
        a3 += a_s[3][n] * xv;
    }
    float* pp = g_part + ((b * NCH + chunk) * H_) * M_ + tid;
    pp[0]      = a0;
    pp[M_]     = a1;
    pp[2 * M_] = a2;
    pp[3 * M_] = a3;
}

// ---------------------------------------------------------------------------
// Kernel 4: reduce partials -> emb (B, H*M)
// ---------------------------------------------------------------------------
__global__ void emb_reduce_kernel(float* __restrict__ out_emb) {
    int idx = blockIdx.x * blockDim.x + threadIdx.x;  // < 32768
    int b  = idx >> 10;
    int hm = idx & 1023;
    float s = 0.0f;
    #pragma unroll
    for (int c = 0; c < NCH; c++)
        s += g_part[(b * NCH + c) * (H_ * M_) + hm];
    out_emb[idx] = s;
}

// ---------------------------------------------------------------------------
extern "C" void kernel_launch(void* const* d_in, const int* in_sizes, int n_in,
                              void* d_out, int out_size) {
    const float* x     = (const float*)d_in[0];
    const float* masks = (const float*)d_in[1];
    const float* V     = (const float*)d_in[2];
    const float* U     = (const float*)d_in[3];
    const float* w     = (const float*)d_in[4];

    float* out     = (float*)d_out;
    float* out_att = out;                        // (H, B, N, 1)
    float* out_emb = out + (size_t)H_ * B_ * N_; // (B, H*M)

    cudaFuncSetAttribute(gemm_logits_kernel,
                         cudaFuncAttributeMaxDynamicSharedMemorySize, SMEM_BYTES);

    prep_kernel<<<PREP_TOT, 1024>>>(x, masks, V, U);

    dim3 g1(H_ * 2, B_, 32 / JGRP);   // (h,nhalf) fastest -> x rows shared via L2
    gemm_logits_kernel<<<g1, 256, SMEM_BYTES>>>(w);

    attn_kernel<<<B_ * H_, 512>>>(masks, out_att);

    emb_partial_kernel<<<dim3(NCH, B_), 256>>>(out_att);

    emb_reduce_kernel<<<32, 1024>>>(out_emb);
}